// round 15
// baseline (speedup 1.0000x reference)
#include <cuda_runtime.h>
#include <cuda_fp16.h>
#include <cuda_bf16.h>
#include <math.h>
#include <stdint.h>

// Problem dims (fixed)
#define BSZ 2
#define SEQ 2048
#define DMODEL 2048
#define NH 32
#define NKV 8
#define HDIM 64
#define QDIM (NH * HDIM)    // 2048
#define KVDIM (NKV * HDIM)  // 512
#define TOKENS (BSZ * SEQ)  // 4096
#define NQKV (QDIM + 2 * KVDIM)  // 3072

// scale = 1/sqrt(64) * log2(e)
#define SCL 0.1803368801111204f

// Scratch (static device globals; allocation is forbidden)
__device__ __half g_xh[(size_t)TOKENS * DMODEL];
__device__ __half g_attnh[(size_t)TOKENS * QDIM];
__device__ __half g_qh[(size_t)TOKENS * QDIM];    // [B][NH][S][64]
__device__ __half g_kh[(size_t)TOKENS * KVDIM];   // [B][NKV][S][64]
__device__ __half g_vth[(size_t)TOKENS * KVDIM];  // [B][NKV][64][S]
__device__ __half g_wqkvTh[(size_t)NQKV * DMODEL];  // [3072][2048] = wqT|wkT|wvT
__device__ __half g_woTh[(size_t)DMODEL * QDIM];

#define MMA16816(d, a0, a1, a2, a3, b0, b1)                      \
    asm volatile(                                                \
        "mma.sync.aligned.m16n8k16.row.col.f32.f16.f16.f32 "     \
        "{%0,%1,%2,%3}, {%4,%5,%6,%7}, {%8,%9}, {%0,%1,%2,%3};"  \
        : "+f"((d)[0]), "+f"((d)[1]), "+f"((d)[2]), "+f"((d)[3]) \
        : "r"(a0), "r"(a1), "r"(a2), "r"(a3), "r"(b0), "r"(b1))

#define CPASYNC16(smem_half_ptr, gptr)                                   \
    asm volatile("cp.async.cg.shared.global [%0], [%1], 16;" ::"r"(      \
                     (uint32_t)__cvta_generic_to_shared(smem_half_ptr)), \
                 "l"(gptr))

// exp2 on FMA/ALU pipes (x <= 0 expected; clamped to >= -126)
__device__ __forceinline__ float fast_exp2(float x) {
    x = fmaxf(x, -126.0f);
    float z = x + 12582912.0f;  // 1.5 * 2^23
    int n = __float_as_int(z) << 23;
    float f = x - (z - 12582912.0f);  // f in [-0.5, 0.5]
    float y = 0.0013276471f;
    y = fmaf(y, f, 0.0096181993f);
    y = fmaf(y, f, 0.0555041086f);
    y = fmaf(y, f, 0.2402264923f);
    y = fmaf(y, f, 0.6931471825f);
    y = fmaf(y, f, 1.0f);
    return __int_as_float(__float_as_int(y) + n);
}

// swizzled index of half element (r, c) in a [rows][64] tile
__device__ __forceinline__ int swi(int r, int c) {
    return r * 64 + ((((c >> 3) ^ (r & 7)) << 3) + (c & 7));
}

// ---------------------------------------------------------------------------
// hgemm4<MODE>: C = A[M,K] @ B[N,K]^T, fp16 in, fp32 accum.
// Round-12 proven: CTA 128x128, BK=32, 2-stage cp.async, 128 thr = 4 warps
// (2m x 2n), warp tile 64x64, scalar LDS fragment loads, static smem.
// Epilogue:
//   MODE 0: fp32 C0[M,N]
//   MODE 4: fused QKV routing by column region:
//     col <  2048        : RoPE + fp16 head-major -> C0 (qh, NH heads)
//     2048 <= col < 2560 : RoPE + fp16 head-major -> C1 (kh, NKV heads)
//     col >= 2560        : fp16 transposed head-major -> C2 (vth, NKV heads)
// ---------------------------------------------------------------------------
template <int MODE>
__global__ __launch_bounds__(128) void hgemm4(const __half* __restrict__ A,
                                              const __half* __restrict__ B,
                                              void* __restrict__ C0,
                                              __half* __restrict__ C1,
                                              __half* __restrict__ C2,
                                              const float* __restrict__ fc,
                                              const float* __restrict__ fs, int M,
                                              int N, int K) {
    __shared__ __half As[2][128][32];
    __shared__ __half Bs[2][128][32];

    const int tid = threadIdx.x;
    const int wid = tid >> 5;
    const int lane = tid & 31;
    const int wm = wid & 1;   // 2 m-warps
    const int wn = wid >> 1;  // 2 n-warps
    const int r = lane >> 2;
    const int tig = lane & 3;
    const int bx = blockIdx.x;
    const int by = blockIdx.y;

    const __half* Ab = A + (size_t)by * 128 * K;
    const __half* Bb = B + (size_t)bx * 128 * K;

    float acc[4][8][4];
#pragma unroll
    for (int mt = 0; mt < 4; mt++)
#pragma unroll
        for (int nt = 0; nt < 8; nt++)
#pragma unroll
            for (int i = 0; i < 4; i++) acc[mt][nt][i] = 0.0f;

#define LOAD_TILE(buf, k0)                                                       \
    {                                                                            \
        for (int i = 0; i < 4; i++) {                                            \
            int cl = tid + i * 128;                                              \
            int row = cl >> 2;                                                   \
            int c = cl & 3;                                                      \
            int phys = (c ^ ((row >> 1) & 3)) * 8;                               \
            CPASYNC16(&As[buf][row][phys], Ab + (size_t)row * K + (k0) + c * 8); \
            CPASYNC16(&Bs[buf][row][phys], Bb + (size_t)row * K + (k0) + c * 8); \
        }                                                                        \
    }

    LOAD_TILE(0, 0);
    asm volatile("cp.async.commit_group;");

    const int nk = K >> 5;
    for (int kt = 0; kt < nk; kt++) {
        const int buf = kt & 1;
        if (kt + 1 < nk) LOAD_TILE(buf ^ 1, (kt + 1) * 32);
        asm volatile("cp.async.commit_group;");
        asm volatile("cp.async.wait_group 1;");
        __syncthreads();

#pragma unroll
        for (int ks = 0; ks < 2; ks++) {
            const int c0 = ks * 2, c1 = ks * 2 + 1;
            uint32_t a[4][4], b[8][2];
#pragma unroll
            for (int mt = 0; mt < 4; mt++) {
                int r0 = wm * 64 + mt * 16 + r;
                int r1 = r0 + 8;
                int s0 = (r0 >> 1) & 3, s1 = (r1 >> 1) & 3;
                a[mt][0] = *(const uint32_t*)&As[buf][r0][(c0 ^ s0) * 8 + tig * 2];
                a[mt][1] = *(const uint32_t*)&As[buf][r1][(c0 ^ s1) * 8 + tig * 2];
                a[mt][2] = *(const uint32_t*)&As[buf][r0][(c1 ^ s0) * 8 + tig * 2];
                a[mt][3] = *(const uint32_t*)&As[buf][r1][(c1 ^ s1) * 8 + tig * 2];
            }
#pragma unroll
            for (int nt = 0; nt < 8; nt++) {
                int n0 = wn * 64 + nt * 8 + r;
                int sn = (n0 >> 1) & 3;
                b[nt][0] = *(const uint32_t*)&Bs[buf][n0][(c0 ^ sn) * 8 + tig * 2];
                b[nt][1] = *(const uint32_t*)&Bs[buf][n0][(c1 ^ sn) * 8 + tig * 2];
            }
#pragma unroll
            for (int mt = 0; mt < 4; mt++)
#pragma unroll
                for (int nt = 0; nt < 8; nt++)
                    MMA16816(acc[mt][nt], a[mt][0], a[mt][1], a[mt][2], a[mt][3],
                             b[nt][0], b[nt][1]);
        }
        __syncthreads();
    }

    // Epilogue
#pragma unroll
    for (int mt = 0; mt < 4; mt++) {
        int row = by * 128 + wm * 64 + mt * 16 + r;  // rows row, row+8
#pragma unroll
        for (int nt = 0; nt < 8; nt++) {
            int col = bx * 128 + wn * 64 + nt * 8 + tig * 2;
            if (MODE == 0) {
                float* C = (float*)C0;
                *(float2*)&C[(size_t)row * N + col] =
                    make_float2(acc[mt][nt][0], acc[mt][nt][1]);
                *(float2*)&C[(size_t)(row + 8) * N + col] =
                    make_float2(acc[mt][nt][2], acc[mt][nt][3]);
            } else {  // MODE 4: fused QKV routing
                int b = row >> 11;
                int s = row & (SEQ - 1);
                if (col < QDIM + KVDIM) {
                    // Q or K: RoPE + head-major
                    __half* base;
                    int c2, nheads;
                    if (col < QDIM) {
                        base = (__half*)C0;
                        c2 = col;
                        nheads = NH;
                    } else {
                        base = C1;
                        c2 = col - QDIM;
                        nheads = NKV;
                    }
                    int h = c2 >> 6;
                    int d = c2 & 63;
                    int j = d >> 1;
                    __half* dst =
                        base + (((size_t)b * nheads + h) * SEQ + s) * HDIM + d;
                    float c0v = fc[s * 32 + j], s0v = fs[s * 32 + j];
                    float c1v = fc[(s + 8) * 32 + j], s1v = fs[(s + 8) * 32 + j];
                    *(__half2*)dst = __floats2half2_rn(
                        acc[mt][nt][0] * c0v - acc[mt][nt][1] * s0v,
                        acc[mt][nt][0] * s0v + acc[mt][nt][1] * c0v);
                    *(__half2*)(dst + 8 * HDIM) = __floats2half2_rn(
                        acc[mt][nt][2] * c1v - acc[mt][nt][3] * s1v,
                        acc[mt][nt][2] * s1v + acc[mt][nt][3] * c1v);
                } else {
                    // V: transposed head-major [b][g][d][S]
                    int c2 = col - QDIM - KVDIM;
                    int h = c2 >> 6;
                    int d = c2 & 63;
                    __half* dst = C2 + (((size_t)b * NKV + h) * HDIM + d) * SEQ + s;
                    dst[0] = __float2half_rn(acc[mt][nt][0]);
                    dst[SEQ] = __float2half_rn(acc[mt][nt][1]);
                    dst[8] = __float2half_rn(acc[mt][nt][2]);
                    dst[SEQ + 8] = __float2half_rn(acc[mt][nt][3]);
                }
            }
        }
    }
#undef LOAD_TILE
}

// ---------------------------------------------------------------------------
// fp32 -> fp16 elementwise convert (n divisible by 4)
// ---------------------------------------------------------------------------
__global__ void f32_to_f16(const float* __restrict__ in, __half* __restrict__ out,
                           int n) {
    int i = (blockIdx.x * blockDim.x + threadIdx.x) * 4;
    if (i >= n) return;
    float4 v = *(const float4*)(in + i);
    *(__half2*)(out + i) = __floats2half2_rn(v.x, v.y);
    *(__half2*)(out + i + 2) = __floats2half2_rn(v.z, v.w);
}

// ---------------------------------------------------------------------------
// Transpose + convert: out[C][R] (fp16) = in[R][C] (fp32)
// ---------------------------------------------------------------------------
__global__ void transpose_f16(const float* __restrict__ in, __half* __restrict__ out,
                              int R, int C) {
    __shared__ float t[32][33];
    int bx = blockIdx.x * 32, by = blockIdx.y * 32;
    int x = bx + threadIdx.x;
    for (int i = threadIdx.y; i < 32; i += 8)
        t[i][threadIdx.x] = in[(size_t)(by + i) * C + x];
    __syncthreads();
    int ox = by + threadIdx.x;
    for (int i = threadIdx.y; i < 32; i += 8)
        out[(size_t)(bx + i) * R + ox] = __float2half_rn(t[threadIdx.x][i]);
}

// ---------------------------------------------------------------------------
// Flash attention v4: q-tile 128, 256 threads = 8 warps x 16 q-rows.
// Per-thread state identical to the proven 64-row/4-warp version; K/V smem
// tiles are shared by 8 warps, halving K/V global/L2 traffic per q-row.
// Qh [b][h][s][64], Kh [b][g][s][64], Vth [b][g][d][S]; out fp16 [tok][h*64+d].
// Smem: Qs 16KB + Ks 2x8KB + Vs 2x8KB = 48KB static.
// ---------------------------------------------------------------------------
__global__ __launch_bounds__(256) void flash_mma3(const __half* __restrict__ Qh,
                                                  const __half* __restrict__ Kh,
                                                  const __half* __restrict__ Vth,
                                                  __half* __restrict__ Oh) {
    __shared__ __half Qs[128 * 64];
    __shared__ __half Ks[2][64 * 64];
    __shared__ __half Vs[2][64 * 64];

    const int bq = gridDim.x - 1 - blockIdx.x;  // heavy blocks first
    const int h = blockIdx.y;
    const int b = blockIdx.z;
    const int g = h >> 2;
    const int tid = threadIdx.x;
    const int wid = tid >> 5;   // 0..7
    const int lane = tid & 31;
    const int r = lane >> 2;
    const int tig = lane & 3;
    const int q0 = bq * 128;
    const int rq = wid * 16;    // warp's 16 q-rows within the tile
    const int ntile = 2 * (bq + 1);

    const __half* qbase = Qh + (((size_t)b * NH + h) * SEQ + q0) * HDIM;
    const __half* kbase = Kh + ((size_t)b * NKV + g) * SEQ * HDIM;
    const __half* vbase = Vth + ((size_t)b * NKV + g) * HDIM * SEQ;

    // Prologue: Q (128x64) + K/V tile 0 (64x64 each); 256 threads
#pragma unroll
    for (int i = 0; i < 4; i++) {
        int cl = i * 256 + tid;
        int rr = cl >> 3, cc = cl & 7;
        int ph = rr * 64 + ((cc ^ (rr & 7)) << 3);
        CPASYNC16(&Qs[ph], qbase + rr * HDIM + cc * 8);
    }
#pragma unroll
    for (int i = 0; i < 2; i++) {
        int cl = i * 256 + tid;
        int rr = cl >> 3, cc = cl & 7;
        int ph = rr * 64 + ((cc ^ (rr & 7)) << 3);
        CPASYNC16(&Ks[0][ph], kbase + rr * HDIM + cc * 8);
        CPASYNC16(&Vs[0][ph], vbase + (size_t)rr * SEQ + cc * 8);
    }
    asm volatile("cp.async.commit_group;");

    uint32_t qa[4][4];
    float m0 = -1e30f, m1 = -1e30f, l0 = 0.0f, l1 = 0.0f;
    float acc[8][4];
#pragma unroll
    for (int dt = 0; dt < 8; dt++)
#pragma unroll
        for (int i = 0; i < 4; i++) acc[dt][i] = 0.0f;

    for (int kt = 0; kt < ntile; kt++) {
        if (kt + 1 < ntile) {
            int nb = (kt + 1) & 1;
            const __half* kb = kbase + (size_t)(kt + 1) * 64 * HDIM;
            const __half* vb = vbase + (kt + 1) * 64;
#pragma unroll
            for (int i = 0; i < 2; i++) {
                int cl = i * 256 + tid;
                int rr = cl >> 3, cc = cl & 7;
                int ph = rr * 64 + ((cc ^ (rr & 7)) << 3);
                CPASYNC16(&Ks[nb][ph], kb + rr * HDIM + cc * 8);
                CPASYNC16(&Vs[nb][ph], vb + (size_t)rr * SEQ + cc * 8);
            }
        }
        asm volatile("cp.async.commit_group;");
        asm volatile("cp.async.wait_group 1;");
        __syncthreads();

        if (kt == 0) {  // Q smem ready (loaded with group 0)
#pragma unroll
            for (int kk = 0; kk < 4; kk++) {
                int c = kk * 16 + tig * 2;
                qa[kk][0] = *(const uint32_t*)&Qs[swi(rq + r, c)];
                qa[kk][1] = *(const uint32_t*)&Qs[swi(rq + r + 8, c)];
                qa[kk][2] = *(const uint32_t*)&Qs[swi(rq + r, c + 8)];
                qa[kk][3] = *(const uint32_t*)&Qs[swi(rq + r + 8, c + 8)];
            }
        }

        const __half* ks = Ks[kt & 1];
        const __half* vs = Vs[kt & 1];

        // S = Q K^T
        float s[8][4];
#pragma unroll
        for (int nt = 0; nt < 8; nt++) {
#pragma unroll
            for (int i = 0; i < 4; i++) s[nt][i] = 0.0f;
#pragma unroll
            for (int kk = 0; kk < 4; kk++) {
                uint32_t b0 = *(const uint32_t*)&ks[swi(nt * 8 + r, kk * 16 + tig * 2)];
                uint32_t b1 =
                    *(const uint32_t*)&ks[swi(nt * 8 + r, kk * 16 + 8 + tig * 2)];
                MMA16816(s[nt], qa[kk][0], qa[kk][1], qa[kk][2], qa[kk][3], b0, b1);
            }
        }

        // scale (+ causal mask when tile can overlap/exceed this warp's rows)
        if (kt * 64 + 63 > q0 + rq) {
            int row_lo = q0 + rq + r, row_hi = row_lo + 8;
#pragma unroll
            for (int nt = 0; nt < 8; nt++) {
                int col = kt * 64 + nt * 8 + tig * 2;
                s[nt][0] = (col > row_lo) ? -1e30f : s[nt][0] * SCL;
                s[nt][1] = (col + 1 > row_lo) ? -1e30f : s[nt][1] * SCL;
                s[nt][2] = (col > row_hi) ? -1e30f : s[nt][2] * SCL;
                s[nt][3] = (col + 1 > row_hi) ? -1e30f : s[nt][3] * SCL;
            }
        } else {
#pragma unroll
            for (int nt = 0; nt < 8; nt++)
#pragma unroll
                for (int i = 0; i < 4; i++) s[nt][i] *= SCL;
        }

        // online softmax (base-2)
        float mt0 = s[0][0], mt1 = s[0][2];
#pragma unroll
        for (int nt = 0; nt < 8; nt++) {
            mt0 = fmaxf(mt0, fmaxf(s[nt][0], s[nt][1]));
            mt1 = fmaxf(mt1, fmaxf(s[nt][2], s[nt][3]));
        }
        mt0 = fmaxf(mt0, __shfl_xor_sync(0xffffffffu, mt0, 1));
        mt0 = fmaxf(mt0, __shfl_xor_sync(0xffffffffu, mt0, 2));
        mt1 = fmaxf(mt1, __shfl_xor_sync(0xffffffffu, mt1, 1));
        mt1 = fmaxf(mt1, __shfl_xor_sync(0xffffffffu, mt1, 2));
        float mn0 = fmaxf(m0, mt0), mn1 = fmaxf(m1, mt1);
        float rs0 = fast_exp2(m0 - mn0), rs1 = fast_exp2(m1 - mn1);
        m0 = mn0;
        m1 = mn1;

        uint32_t ph[8][2];
        float sum0 = 0.0f, sum1 = 0.0f;
#pragma unroll
        for (int nt = 0; nt < 8; nt++) {
            float p0 = fast_exp2(s[nt][0] - mn0);
            float p1 = fast_exp2(s[nt][1] - mn0);
            float p2 = fast_exp2(s[nt][2] - mn1);
            float p3 = fast_exp2(s[nt][3] - mn1);
            sum0 += p0 + p1;
            sum1 += p2 + p3;
            __half2 h01 = __floats2half2_rn(p0, p1);
            __half2 h23 = __floats2half2_rn(p2, p3);
            ph[nt][0] = *(uint32_t*)&h01;
            ph[nt][1] = *(uint32_t*)&h23;
        }
        sum0 += __shfl_xor_sync(0xffffffffu, sum0, 1);
        sum0 += __shfl_xor_sync(0xffffffffu, sum0, 2);
        sum1 += __shfl_xor_sync(0xffffffffu, sum1, 1);
        sum1 += __shfl_xor_sync(0xffffffffu, sum1, 2);
        l0 = l0 * rs0 + sum0;
        l1 = l1 * rs1 + sum1;

#pragma unroll
        for (int dt = 0; dt < 8; dt++) {
            acc[dt][0] *= rs0;
            acc[dt][1] *= rs0;
            acc[dt][2] *= rs1;
            acc[dt][3] *= rs1;
        }

        // O += P @ V  (Vt stored [d][kv])
#pragma unroll
        for (int dt = 0; dt < 8; dt++) {
#pragma unroll
            for (int kk = 0; kk < 4; kk++) {
                uint32_t b0 = *(const uint32_t*)&vs[swi(dt * 8 + r, kk * 16 + tig * 2)];
                uint32_t b1 =
                    *(const uint32_t*)&vs[swi(dt * 8 + r, kk * 16 + 8 + tig * 2)];
                MMA16816(acc[dt], ph[2 * kk][0], ph[2 * kk][1], ph[2 * kk + 1][0],
                         ph[2 * kk + 1][1], b0, b1);
            }
        }
        __syncthreads();  // done with this buffer before it is refilled
    }

    // normalize + write fp16
    float inv0 = 1.0f / l0, inv1 = 1.0f / l1;
    __half* obase = Oh + ((size_t)b * SEQ + q0 + rq) * QDIM + h * HDIM;
#pragma unroll
    for (int dt = 0; dt < 8; dt++) {
        int col = dt * 8 + tig * 2;
        *(__half2*)(obase + (size_t)r * QDIM + col) =
            __floats2half2_rn(acc[dt][0] * inv0, acc[dt][1] * inv0);
        *(__half2*)(obase + (size_t)(r + 8) * QDIM + col) =
            __floats2half2_rn(acc[dt][2] * inv1, acc[dt][3] * inv1);
    }
}

// ---------------------------------------------------------------------------
// Launch
// ---------------------------------------------------------------------------
extern "C" void kernel_launch(void* const* d_in, const int* in_sizes, int n_in,
                              void* d_out, int out_size) {
    const float* x = (const float*)d_in[0];
    const float* wq = (const float*)d_in[1];
    const float* wk = (const float*)d_in[2];
    const float* wv = (const float*)d_in[3];
    const float* wo = (const float*)d_in[4];
    const float* fc = (const float*)d_in[5];
    const float* fs = (const float*)d_in[6];
    float* out = (float*)d_out;

    __half *xh, *attnh, *qh, *kh, *vth, *wqkvTh, *woTh;
    cudaGetSymbolAddress((void**)&xh, g_xh);
    cudaGetSymbolAddress((void**)&attnh, g_attnh);
    cudaGetSymbolAddress((void**)&qh, g_qh);
    cudaGetSymbolAddress((void**)&kh, g_kh);
    cudaGetSymbolAddress((void**)&vth, g_vth);
    cudaGetSymbolAddress((void**)&wqkvTh, g_wqkvTh);
    cudaGetSymbolAddress((void**)&woTh, g_woTh);

    // x -> fp16; weights -> concatenated [3072][2048] fp16 (wqT | wkT | wvT)
    {
        int n = TOKENS * DMODEL;
        f32_to_f16<<<(n / 4 + 255) / 256, 256>>>(x, xh, n);
    }
    transpose_f16<<<dim3(QDIM / 32, DMODEL / 32), dim3(32, 8)>>>(wq, wqkvTh, DMODEL,
                                                                 QDIM);
    transpose_f16<<<dim3(KVDIM / 32, DMODEL / 32), dim3(32, 8)>>>(
        wk, wqkvTh + (size_t)QDIM * DMODEL, DMODEL, KVDIM);
    transpose_f16<<<dim3(KVDIM / 32, DMODEL / 32), dim3(32, 8)>>>(
        wv, wqkvTh + (size_t)(QDIM + KVDIM) * DMODEL, DMODEL, KVDIM);
    transpose_f16<<<dim3(DMODEL / 32, QDIM / 32), dim3(32, 8)>>>(wo, woTh, QDIM,
                                                                 DMODEL);

    // Fused QKV projection: one GEMM, epilogue routes Q(RoPE)/K(RoPE)/V(transp)
    hgemm4<4><<<dim3(NQKV / 128, TOKENS / 128), 128>>>(
        xh, wqkvTh, qh, kh, vth, fc, fs, TOKENS, NQKV, DMODEL);

    // Flash attention v4 (q-tile 128, 8 warps) -> attnh fp16
    flash_mma3<<<dim3(SEQ / 128, NH, BSZ), 256>>>(qh, kh, vth, attnh);

    // Output projection -> fp32 out
    hgemm4<0><<<dim3(DMODEL / 128, TOKENS / 128), 128>>>(
        attnh, woTh, out, (__half*)0, (__half*)0, fc, fs, TOKENS, DMODEL, QDIM);
}

// round 16
// speedup vs baseline: 1.0665x; 1.0665x over previous
#include <cuda_runtime.h>
#include <cuda_fp16.h>
#include <cuda_bf16.h>
#include <math.h>
#include <stdint.h>

// Problem dims (fixed)
#define BSZ 2
#define SEQ 2048
#define DMODEL 2048
#define NH 32
#define NKV 8
#define HDIM 64
#define QDIM (NH * HDIM)    // 2048
#define KVDIM (NKV * HDIM)  // 512
#define TOKENS (BSZ * SEQ)  // 4096
#define NQKV (QDIM + 2 * KVDIM)  // 3072

// scale = 1/sqrt(64) * log2(e)
#define SCL 0.1803368801111204f

// Scratch (static device globals; allocation is forbidden)
__device__ __half g_xh[(size_t)TOKENS * DMODEL];
__device__ __half g_attnh[(size_t)TOKENS * QDIM];
__device__ __half g_qh[(size_t)TOKENS * QDIM];    // [B][NH][S][64]
__device__ __half g_kh[(size_t)TOKENS * KVDIM];   // [B][NKV][S][64]
__device__ __half g_vth[(size_t)TOKENS * KVDIM];  // [B][NKV][64][S]
__device__ __half g_wqkvTh[(size_t)NQKV * DMODEL];  // [3072][2048] = wqT|wkT|wvT
__device__ __half g_woTh[(size_t)DMODEL * QDIM];

#define MMA16816(d, a0, a1, a2, a3, b0, b1)                      \
    asm volatile(                                                \
        "mma.sync.aligned.m16n8k16.row.col.f32.f16.f16.f32 "     \
        "{%0,%1,%2,%3}, {%4,%5,%6,%7}, {%8,%9}, {%0,%1,%2,%3};"  \
        : "+f"((d)[0]), "+f"((d)[1]), "+f"((d)[2]), "+f"((d)[3]) \
        : "r"(a0), "r"(a1), "r"(a2), "r"(a3), "r"(b0), "r"(b1))

#define CPASYNC16(smem_half_ptr, gptr)                                   \
    asm volatile("cp.async.cg.shared.global [%0], [%1], 16;" ::"r"(      \
                     (uint32_t)__cvta_generic_to_shared(smem_half_ptr)), \
                 "l"(gptr))

// exp2 on FMA/ALU pipes (x <= 0 expected; clamped to >= -126)
__device__ __forceinline__ float fast_exp2(float x) {
    x = fmaxf(x, -126.0f);
    float z = x + 12582912.0f;  // 1.5 * 2^23
    int n = __float_as_int(z) << 23;
    float f = x - (z - 12582912.0f);  // f in [-0.5, 0.5]
    float y = 0.0013276471f;
    y = fmaf(y, f, 0.0096181993f);
    y = fmaf(y, f, 0.0555041086f);
    y = fmaf(y, f, 0.2402264923f);
    y = fmaf(y, f, 0.6931471825f);
    y = fmaf(y, f, 1.0f);
    return __int_as_float(__float_as_int(y) + n);
}

// swizzled index of half element (r, c) in a [rows][64] tile
__device__ __forceinline__ int swi(int r, int c) {
    return r * 64 + ((((c >> 3) ^ (r & 7)) << 3) + (c & 7));
}

// ---------------------------------------------------------------------------
// hgemm4<MODE>: C = A[M,K] @ B[N,K]^T, fp16 in, fp32 accum.
// Round-12 proven: CTA 128x128, BK=32, 2-stage cp.async, 128 thr = 4 warps
// (2m x 2n), warp tile 64x64, scalar LDS fragment loads, static smem.
// Epilogue:
//   MODE 0: fp32 C0[M,N]
//   MODE 4: fused QKV routing by column region:
//     col <  2048        : RoPE + fp16 head-major -> C0 (qh, NH heads)
//     2048 <= col < 2560 : RoPE + fp16 head-major -> C1 (kh, NKV heads)
//     col >= 2560        : fp16 transposed head-major -> C2 (vth, NKV heads)
// ---------------------------------------------------------------------------
template <int MODE>
__global__ __launch_bounds__(128) void hgemm4(const __half* __restrict__ A,
                                              const __half* __restrict__ B,
                                              void* __restrict__ C0,
                                              __half* __restrict__ C1,
                                              __half* __restrict__ C2,
                                              const float* __restrict__ fc,
                                              const float* __restrict__ fs, int M,
                                              int N, int K) {
    __shared__ __half As[2][128][32];
    __shared__ __half Bs[2][128][32];

    const int tid = threadIdx.x;
    const int wid = tid >> 5;
    const int lane = tid & 31;
    const int wm = wid & 1;   // 2 m-warps
    const int wn = wid >> 1;  // 2 n-warps
    const int r = lane >> 2;
    const int tig = lane & 3;
    const int bx = blockIdx.x;
    const int by = blockIdx.y;

    const __half* Ab = A + (size_t)by * 128 * K;
    const __half* Bb = B + (size_t)bx * 128 * K;

    float acc[4][8][4];
#pragma unroll
    for (int mt = 0; mt < 4; mt++)
#pragma unroll
        for (int nt = 0; nt < 8; nt++)
#pragma unroll
            for (int i = 0; i < 4; i++) acc[mt][nt][i] = 0.0f;

#define LOAD_TILE(buf, k0)                                                       \
    {                                                                            \
        for (int i = 0; i < 4; i++) {                                            \
            int cl = tid + i * 128;                                              \
            int row = cl >> 2;                                                   \
            int c = cl & 3;                                                      \
            int phys = (c ^ ((row >> 1) & 3)) * 8;                               \
            CPASYNC16(&As[buf][row][phys], Ab + (size_t)row * K + (k0) + c * 8); \
            CPASYNC16(&Bs[buf][row][phys], Bb + (size_t)row * K + (k0) + c * 8); \
        }                                                                        \
    }

    LOAD_TILE(0, 0);
    asm volatile("cp.async.commit_group;");

    const int nk = K >> 5;
    for (int kt = 0; kt < nk; kt++) {
        const int buf = kt & 1;
        if (kt + 1 < nk) LOAD_TILE(buf ^ 1, (kt + 1) * 32);
        asm volatile("cp.async.commit_group;");
        asm volatile("cp.async.wait_group 1;");
        __syncthreads();

#pragma unroll
        for (int ks = 0; ks < 2; ks++) {
            const int c0 = ks * 2, c1 = ks * 2 + 1;
            uint32_t a[4][4], b[8][2];
#pragma unroll
            for (int mt = 0; mt < 4; mt++) {
                int r0 = wm * 64 + mt * 16 + r;
                int r1 = r0 + 8;
                int s0 = (r0 >> 1) & 3, s1 = (r1 >> 1) & 3;
                a[mt][0] = *(const uint32_t*)&As[buf][r0][(c0 ^ s0) * 8 + tig * 2];
                a[mt][1] = *(const uint32_t*)&As[buf][r1][(c0 ^ s1) * 8 + tig * 2];
                a[mt][2] = *(const uint32_t*)&As[buf][r0][(c1 ^ s0) * 8 + tig * 2];
                a[mt][3] = *(const uint32_t*)&As[buf][r1][(c1 ^ s1) * 8 + tig * 2];
            }
#pragma unroll
            for (int nt = 0; nt < 8; nt++) {
                int n0 = wn * 64 + nt * 8 + r;
                int sn = (n0 >> 1) & 3;
                b[nt][0] = *(const uint32_t*)&Bs[buf][n0][(c0 ^ sn) * 8 + tig * 2];
                b[nt][1] = *(const uint32_t*)&Bs[buf][n0][(c1 ^ sn) * 8 + tig * 2];
            }
#pragma unroll
            for (int mt = 0; mt < 4; mt++)
#pragma unroll
                for (int nt = 0; nt < 8; nt++)
                    MMA16816(acc[mt][nt], a[mt][0], a[mt][1], a[mt][2], a[mt][3],
                             b[nt][0], b[nt][1]);
        }
        __syncthreads();
    }

    // Epilogue
#pragma unroll
    for (int mt = 0; mt < 4; mt++) {
        int row = by * 128 + wm * 64 + mt * 16 + r;  // rows row, row+8
#pragma unroll
        for (int nt = 0; nt < 8; nt++) {
            int col = bx * 128 + wn * 64 + nt * 8 + tig * 2;
            if (MODE == 0) {
                float* C = (float*)C0;
                *(float2*)&C[(size_t)row * N + col] =
                    make_float2(acc[mt][nt][0], acc[mt][nt][1]);
                *(float2*)&C[(size_t)(row + 8) * N + col] =
                    make_float2(acc[mt][nt][2], acc[mt][nt][3]);
            } else {  // MODE 4: fused QKV routing
                int b = row >> 11;
                int s = row & (SEQ - 1);
                if (col < QDIM + KVDIM) {
                    // Q or K: RoPE + head-major
                    __half* base;
                    int c2, nheads;
                    if (col < QDIM) {
                        base = (__half*)C0;
                        c2 = col;
                        nheads = NH;
                    } else {
                        base = C1;
                        c2 = col - QDIM;
                        nheads = NKV;
                    }
                    int h = c2 >> 6;
                    int d = c2 & 63;
                    int j = d >> 1;
                    __half* dst =
                        base + (((size_t)b * nheads + h) * SEQ + s) * HDIM + d;
                    float c0v = fc[s * 32 + j], s0v = fs[s * 32 + j];
                    float c1v = fc[(s + 8) * 32 + j], s1v = fs[(s + 8) * 32 + j];
                    *(__half2*)dst = __floats2half2_rn(
                        acc[mt][nt][0] * c0v - acc[mt][nt][1] * s0v,
                        acc[mt][nt][0] * s0v + acc[mt][nt][1] * c0v);
                    *(__half2*)(dst + 8 * HDIM) = __floats2half2_rn(
                        acc[mt][nt][2] * c1v - acc[mt][nt][3] * s1v,
                        acc[mt][nt][2] * s1v + acc[mt][nt][3] * c1v);
                } else {
                    // V: transposed head-major [b][g][d][S]
                    int c2 = col - QDIM - KVDIM;
                    int h = c2 >> 6;
                    int d = c2 & 63;
                    __half* dst = C2 + (((size_t)b * NKV + h) * HDIM + d) * SEQ + s;
                    dst[0] = __float2half_rn(acc[mt][nt][0]);
                    dst[SEQ] = __float2half_rn(acc[mt][nt][1]);
                    dst[8] = __float2half_rn(acc[mt][nt][2]);
                    dst[SEQ + 8] = __float2half_rn(acc[mt][nt][3]);
                }
            }
        }
    }
#undef LOAD_TILE
}

// ---------------------------------------------------------------------------
// fp32 -> fp16 elementwise convert (n divisible by 4)
// ---------------------------------------------------------------------------
__global__ void f32_to_f16(const float* __restrict__ in, __half* __restrict__ out,
                           int n) {
    int i = (blockIdx.x * blockDim.x + threadIdx.x) * 4;
    if (i >= n) return;
    float4 v = *(const float4*)(in + i);
    *(__half2*)(out + i) = __floats2half2_rn(v.x, v.y);
    *(__half2*)(out + i + 2) = __floats2half2_rn(v.z, v.w);
}

// ---------------------------------------------------------------------------
// Fused QKV weight transpose+convert into the concatenated [3072][2048] fp16
// buffer: z selects wq (2048 cols) / wk / wv (512 cols each).
// Grid: (DMODEL/32 rows always valid, 64 x-tiles; wk/wv blocks with
// bx >= 16 exit immediately).
// ---------------------------------------------------------------------------
__global__ void transpose_qkv_f16(const float* __restrict__ wq,
                                  const float* __restrict__ wk,
                                  const float* __restrict__ wv,
                                  __half* __restrict__ out) {
    __shared__ float t[32][33];
    int z = blockIdx.z;
    const float* in = (z == 0) ? wq : (z == 1) ? wk : wv;
    int C = (z == 0) ? QDIM : KVDIM;  // input column count
    if (blockIdx.x * 32 >= C) return;
    __half* dst = out + (size_t)((z == 0) ? 0 : (z == 1) ? QDIM : QDIM + KVDIM) *
                            DMODEL;
    int bx = blockIdx.x * 32, by = blockIdx.y * 32;
    int x = bx + threadIdx.x;
    for (int i = threadIdx.y; i < 32; i += 8)
        t[i][threadIdx.x] = in[(size_t)(by + i) * C + x];
    __syncthreads();
    int ox = by + threadIdx.x;
    for (int i = threadIdx.y; i < 32; i += 8)
        dst[(size_t)(bx + i) * DMODEL + ox] = __float2half_rn(t[threadIdx.x][i]);
}

// ---------------------------------------------------------------------------
// Transpose + convert: out[C][R] (fp16) = in[R][C] (fp32)   (for wo)
// ---------------------------------------------------------------------------
__global__ void transpose_f16(const float* __restrict__ in, __half* __restrict__ out,
                              int R, int C) {
    __shared__ float t[32][33];
    int bx = blockIdx.x * 32, by = blockIdx.y * 32;
    int x = bx + threadIdx.x;
    for (int i = threadIdx.y; i < 32; i += 8)
        t[i][threadIdx.x] = in[(size_t)(by + i) * C + x];
    __syncthreads();
    int ox = by + threadIdx.x;
    for (int i = threadIdx.y; i < 32; i += 8)
        out[(size_t)(bx + i) * R + ox] = __float2half_rn(t[threadIdx.x][i]);
}

// ---------------------------------------------------------------------------
// Flash attention, fp16 mma.sync, causal, GQA (round-12 proven, verbatim).
// Block: 64 q-rows x 1 head; 128 threads (4 warps x m16).
// Qh [b][h][s][64], Kh [b][g][s][64], Vth [b][g][d][S]; out fp16 [tok][h*64+d].
// ---------------------------------------------------------------------------
__global__ __launch_bounds__(128) void flash_mma(const __half* __restrict__ Qh,
                                                 const __half* __restrict__ Kh,
                                                 const __half* __restrict__ Vth,
                                                 __half* __restrict__ Oh) {
    __shared__ __half Qs[64 * 64];
    __shared__ __half Ks[2][64 * 64];
    __shared__ __half Vs[2][64 * 64];

    const int bq = gridDim.x - 1 - blockIdx.x;  // heavy blocks first
    const int h = blockIdx.y;
    const int b = blockIdx.z;
    const int g = h >> 2;
    const int tid = threadIdx.x;
    const int wid = tid >> 5;
    const int lane = tid & 31;
    const int r = lane >> 2;
    const int tig = lane & 3;
    const int q0 = bq * 64;
    const int rq = wid * 16;
    const int ntile = bq + 1;

    const __half* qbase = Qh + (((size_t)b * NH + h) * SEQ + q0) * HDIM;
    const __half* kbase = Kh + ((size_t)b * NKV + g) * SEQ * HDIM;
    const __half* vbase = Vth + ((size_t)b * NKV + g) * HDIM * SEQ;

    // Prologue: Q + K/V tile 0
#pragma unroll
    for (int i = 0; i < 4; i++) {
        int cl = i * 128 + tid;
        int rr = cl >> 3, cc = cl & 7;
        int ph = rr * 64 + ((cc ^ (rr & 7)) << 3);
        CPASYNC16(&Qs[ph], qbase + rr * HDIM + cc * 8);
        CPASYNC16(&Ks[0][ph], kbase + rr * HDIM + cc * 8);
        CPASYNC16(&Vs[0][ph], vbase + (size_t)rr * SEQ + cc * 8);
    }
    asm volatile("cp.async.commit_group;");

    uint32_t qa[4][4];
    float m0 = -1e30f, m1 = -1e30f, l0 = 0.0f, l1 = 0.0f;
    float acc[8][4];
#pragma unroll
    for (int dt = 0; dt < 8; dt++)
#pragma unroll
        for (int i = 0; i < 4; i++) acc[dt][i] = 0.0f;

    for (int kt = 0; kt < ntile; kt++) {
        if (kt + 1 < ntile) {
            int nb = (kt + 1) & 1;
            const __half* kb = kbase + (size_t)(kt + 1) * 64 * HDIM;
            const __half* vb = vbase + (kt + 1) * 64;
#pragma unroll
            for (int i = 0; i < 4; i++) {
                int cl = i * 128 + tid;
                int rr = cl >> 3, cc = cl & 7;
                int ph = rr * 64 + ((cc ^ (rr & 7)) << 3);
                CPASYNC16(&Ks[nb][ph], kb + rr * HDIM + cc * 8);
                CPASYNC16(&Vs[nb][ph], vb + (size_t)rr * SEQ + cc * 8);
            }
        }
        asm volatile("cp.async.commit_group;");
        asm volatile("cp.async.wait_group 1;");
        __syncthreads();

        if (kt == 0) {  // Q smem ready (loaded with group 0)
#pragma unroll
            for (int kk = 0; kk < 4; kk++) {
                int c = kk * 16 + tig * 2;
                qa[kk][0] = *(const uint32_t*)&Qs[swi(rq + r, c)];
                qa[kk][1] = *(const uint32_t*)&Qs[swi(rq + r + 8, c)];
                qa[kk][2] = *(const uint32_t*)&Qs[swi(rq + r, c + 8)];
                qa[kk][3] = *(const uint32_t*)&Qs[swi(rq + r + 8, c + 8)];
            }
        }

        const __half* ks = Ks[kt & 1];
        const __half* vs = Vs[kt & 1];

        // S = Q K^T
        float s[8][4];
#pragma unroll
        for (int nt = 0; nt < 8; nt++) {
#pragma unroll
            for (int i = 0; i < 4; i++) s[nt][i] = 0.0f;
#pragma unroll
            for (int kk = 0; kk < 4; kk++) {
                uint32_t b0 = *(const uint32_t*)&ks[swi(nt * 8 + r, kk * 16 + tig * 2)];
                uint32_t b1 =
                    *(const uint32_t*)&ks[swi(nt * 8 + r, kk * 16 + 8 + tig * 2)];
                MMA16816(s[nt], qa[kk][0], qa[kk][1], qa[kk][2], qa[kk][3], b0, b1);
            }
        }

        // scale (+ causal mask on diagonal tile)
        if (kt == bq) {
            int row_lo = q0 + rq + r, row_hi = row_lo + 8;
#pragma unroll
            for (int nt = 0; nt < 8; nt++) {
                int col = kt * 64 + nt * 8 + tig * 2;
                s[nt][0] = (col > row_lo) ? -1e30f : s[nt][0] * SCL;
                s[nt][1] = (col + 1 > row_lo) ? -1e30f : s[nt][1] * SCL;
                s[nt][2] = (col > row_hi) ? -1e30f : s[nt][2] * SCL;
                s[nt][3] = (col + 1 > row_hi) ? -1e30f : s[nt][3] * SCL;
            }
        } else {
#pragma unroll
            for (int nt = 0; nt < 8; nt++)
#pragma unroll
                for (int i = 0; i < 4; i++) s[nt][i] *= SCL;
        }

        // online softmax (base-2)
        float mt0 = s[0][0], mt1 = s[0][2];
#pragma unroll
        for (int nt = 0; nt < 8; nt++) {
            mt0 = fmaxf(mt0, fmaxf(s[nt][0], s[nt][1]));
            mt1 = fmaxf(mt1, fmaxf(s[nt][2], s[nt][3]));
        }
        mt0 = fmaxf(mt0, __shfl_xor_sync(0xffffffffu, mt0, 1));
        mt0 = fmaxf(mt0, __shfl_xor_sync(0xffffffffu, mt0, 2));
        mt1 = fmaxf(mt1, __shfl_xor_sync(0xffffffffu, mt1, 1));
        mt1 = fmaxf(mt1, __shfl_xor_sync(0xffffffffu, mt1, 2));
        float mn0 = fmaxf(m0, mt0), mn1 = fmaxf(m1, mt1);
        float rs0 = fast_exp2(m0 - mn0), rs1 = fast_exp2(m1 - mn1);
        m0 = mn0;
        m1 = mn1;

        uint32_t ph[8][2];
        float sum0 = 0.0f, sum1 = 0.0f;
#pragma unroll
        for (int nt = 0; nt < 8; nt++) {
            float p0 = fast_exp2(s[nt][0] - mn0);
            float p1 = fast_exp2(s[nt][1] - mn0);
            float p2 = fast_exp2(s[nt][2] - mn1);
            float p3 = fast_exp2(s[nt][3] - mn1);
            sum0 += p0 + p1;
            sum1 += p2 + p3;
            __half2 h01 = __floats2half2_rn(p0, p1);
            __half2 h23 = __floats2half2_rn(p2, p3);
            ph[nt][0] = *(uint32_t*)&h01;
            ph[nt][1] = *(uint32_t*)&h23;
        }
        sum0 += __shfl_xor_sync(0xffffffffu, sum0, 1);
        sum0 += __shfl_xor_sync(0xffffffffu, sum0, 2);
        sum1 += __shfl_xor_sync(0xffffffffu, sum1, 1);
        sum1 += __shfl_xor_sync(0xffffffffu, sum1, 2);
        l0 = l0 * rs0 + sum0;
        l1 = l1 * rs1 + sum1;

#pragma unroll
        for (int dt = 0; dt < 8; dt++) {
            acc[dt][0] *= rs0;
            acc[dt][1] *= rs0;
            acc[dt][2] *= rs1;
            acc[dt][3] *= rs1;
        }

        // O += P @ V  (Vt stored [d][kv])
#pragma unroll
        for (int dt = 0; dt < 8; dt++) {
#pragma unroll
            for (int kk = 0; kk < 4; kk++) {
                uint32_t b0 = *(const uint32_t*)&vs[swi(dt * 8 + r, kk * 16 + tig * 2)];
                uint32_t b1 =
                    *(const uint32_t*)&vs[swi(dt * 8 + r, kk * 16 + 8 + tig * 2)];
                MMA16816(acc[dt], ph[2 * kk][0], ph[2 * kk][1], ph[2 * kk + 1][0],
                         ph[2 * kk + 1][1], b0, b1);
            }
        }
        __syncthreads();  // done with this buffer before it is refilled
    }

    // normalize + write fp16
    float inv0 = 1.0f / l0, inv1 = 1.0f / l1;
    __half* obase = Oh + ((size_t)b * SEQ + q0 + rq) * QDIM + h * HDIM;
#pragma unroll
    for (int dt = 0; dt < 8; dt++) {
        int col = dt * 8 + tig * 2;
        *(__half2*)(obase + (size_t)r * QDIM + col) =
            __floats2half2_rn(acc[dt][0] * inv0, acc[dt][1] * inv0);
        *(__half2*)(obase + (size_t)(r + 8) * QDIM + col) =
            __floats2half2_rn(acc[dt][2] * inv1, acc[dt][3] * inv1);
    }
}

// ---------------------------------------------------------------------------
// Launch
// ---------------------------------------------------------------------------
extern "C" void kernel_launch(void* const* d_in, const int* in_sizes, int n_in,
                              void* d_out, int out_size) {
    const float* x = (const float*)d_in[0];
    const float* wq = (const float*)d_in[1];
    const float* wk = (const float*)d_in[2];
    const float* wv = (const float*)d_in[3];
    const float* wo = (const float*)d_in[4];
    const float* fc = (const float*)d_in[5];
    const float* fs = (const float*)d_in[6];
    float* out = (float*)d_out;

    __half *xh, *attnh, *qh, *kh, *vth, *wqkvTh, *woTh;
    cudaGetSymbolAddress((void**)&xh, g_xh);
    cudaGetSymbolAddress((void**)&attnh, g_attnh);
    cudaGetSymbolAddress((void**)&qh, g_qh);
    cudaGetSymbolAddress((void**)&kh, g_kh);
    cudaGetSymbolAddress((void**)&vth, g_vth);
    cudaGetSymbolAddress((void**)&wqkvTh, g_wqkvTh);
    cudaGetSymbolAddress((void**)&woTh, g_woTh);

    // x -> fp16; weights -> concatenated [3072][2048] fp16 (wqT | wkT | wvT)
    {
        int n = TOKENS * DMODEL;
        f32_to_f16<<<(n / 4 + 255) / 256, 256>>>(x, xh, n);
    }
    transpose_qkv_f16<<<dim3(QDIM / 32, DMODEL / 32, 3), dim3(32, 8)>>>(wq, wk, wv,
                                                                        wqkvTh);
    transpose_f16<<<dim3(DMODEL / 32, QDIM / 32), dim3(32, 8)>>>(wo, woTh, QDIM,
                                                                 DMODEL);

    // Fused QKV projection: one GEMM, epilogue routes Q(RoPE)/K(RoPE)/V(transp)
    hgemm4<4><<<dim3(NQKV / 128, TOKENS / 128), 128>>>(
        xh, wqkvTh, qh, kh, vth, fc, fs, TOKENS, NQKV, DMODEL);

    // Flash attention (round-12 proven, 64-row q-tile) -> attnh fp16
    flash_mma<<<dim3(SEQ / 64, NH, BSZ), 128>>>(qh, kh, vth, attnh);

    // Output projection -> fp32 out
    hgemm4<0><<<dim3(DMODEL / 128, TOKENS / 128), 128>>>(
        attnh, woTh, out, (__half*)0, (__half*)0, fc, fs, TOKENS, DMODEL, QDIM);
}